// round 1
// baseline (speedup 1.0000x reference)
#include <cuda_runtime.h>
#include <math.h>

// Problem constants
#define B_   8
#define DIM  192
#define QKV  576     // 3*DIM
#define NH   8
#define CH   24      // DIM / NH
#define H_   128
#define W_   128
#define HW   16384

// Scratch (device globals; no allocation allowed)
__device__ float g_qkv[B_ * QKV * HW];   // after 1x1 conv
__device__ float g_dw [B_ * QKV * HW];   // after depthwise conv
__device__ float g_ssq[B_ * DIM];        // sum of squares of q rows
__device__ float g_ssk[B_ * DIM];        // sum of squares of k rows
__device__ float g_S  [B_ * NH * CH * CH]; // raw Gram matrices
__device__ float g_M  [B_ * DIM * DIM];  // W_proj @ blockdiag(attn)

// ---------------------------------------------------------------------------
// Zero accumulators (g_S via atomics, g_ssq/g_ssk via atomics from 2 blocks)
// ---------------------------------------------------------------------------
__global__ void zero_kernel() {
    int i = blockIdx.x * blockDim.x + threadIdx.x;
    if (i < B_ * NH * CH * CH) g_S[i] = 0.f;
    if (i < B_ * DIM) { g_ssq[i] = 0.f; g_ssk[i] = 0.f; }
}

// ---------------------------------------------------------------------------
// SGEMM: C[M,N] = A[M,K] @ B[K,N], per-batch via blockIdx.z.
// Tile: BM=64, BN=128, BK=16. 256 threads, each computes 4x8.
// mode 0: A = w_qkv (shared),   B = x + z*DIM*HW,            C = g_qkv + z*QKV*HW
// mode 1: A = g_M + z*DIM*DIM,  B = g_dw + z*QKV*HW + 2*DIM*HW (v), C = out + z*DIM*HW
// K = DIM = 192, lda = DIM, ldb = ldc = HW for both modes.
// ---------------------------------------------------------------------------
__global__ __launch_bounds__(256) void sgemm_kernel(
    int mode, const float* __restrict__ Aext, const float* __restrict__ Bext,
    float* __restrict__ Cext)
{
    __shared__ float As[16][64];
    __shared__ float Bs[16][128];

    const int z = blockIdx.z;
    const float* A;
    const float* Bb;
    float* Cb;
    if (mode == 0) {
        A  = Aext;                                   // w_qkv [576][192]
        Bb = Bext + (long)z * DIM * HW;              // x[z]
        Cb = g_qkv + (long)z * QKV * HW;
    } else {
        A  = g_M + (long)z * DIM * DIM;
        Bb = g_dw + (long)z * QKV * HW + (long)(2 * DIM) * HW;  // v part
        Cb = Cext + (long)z * DIM * HW;
    }
    const float* Ab = A + (long)blockIdx.y * 64 * DIM;
    Bb += blockIdx.x * 128;
    Cb += (long)blockIdx.y * 64 * HW + blockIdx.x * 128;

    const int t  = threadIdx.x;
    const int tx = t & 15;        // 0..15 -> col group (x8)
    const int ty = t >> 4;        // 0..15 -> row group (x4)
    const int ac = t & 15;        // A load: k within tile
    const int ar = t >> 4;        // A load: row base (step 16)
    const int bc = (t & 31) << 2; // B load: float4 col
    const int br = t >> 5;        // B load: row base (step 8)

    float acc[4][8];
    #pragma unroll
    for (int i = 0; i < 4; i++)
        #pragma unroll
        for (int j = 0; j < 8; j++) acc[i][j] = 0.f;

    for (int k0 = 0; k0 < DIM; k0 += 16) {
        #pragma unroll
        for (int r = 0; r < 64; r += 16)
            As[ac][ar + r] = Ab[(ar + r) * DIM + k0 + ac];
        #pragma unroll
        for (int r = 0; r < 16; r += 8)
            *(float4*)&Bs[br + r][bc] =
                *(const float4*)&Bb[(long)(k0 + br + r) * HW + bc];
        __syncthreads();
        #pragma unroll
        for (int kk = 0; kk < 16; kk++) {
            float4 a4 = *(float4*)&As[kk][ty * 4];
            float4 b0 = *(float4*)&Bs[kk][tx * 8];
            float4 b1 = *(float4*)&Bs[kk][tx * 8 + 4];
            float av[4] = {a4.x, a4.y, a4.z, a4.w};
            float bv[8] = {b0.x, b0.y, b0.z, b0.w, b1.x, b1.y, b1.z, b1.w};
            #pragma unroll
            for (int i = 0; i < 4; i++)
                #pragma unroll
                for (int j = 0; j < 8; j++)
                    acc[i][j] += av[i] * bv[j];
        }
        __syncthreads();
    }
    #pragma unroll
    for (int i = 0; i < 4; i++) {
        float4 c0 = make_float4(acc[i][0], acc[i][1], acc[i][2], acc[i][3]);
        float4 c1 = make_float4(acc[i][4], acc[i][5], acc[i][6], acc[i][7]);
        *(float4*)&Cb[(long)(ty * 4 + i) * HW + tx * 8]     = c0;
        *(float4*)&Cb[(long)(ty * 4 + i) * HW + tx * 8 + 4] = c1;
    }
}

// ---------------------------------------------------------------------------
// Depthwise 3x3, dilation 2, pad 2. One block = (b, ch, half-image of 64 rows).
// Loads 68 rows (with zeroed halo) into smem; also accumulates sum-of-squares
// for q/k channels (fused, one atomicAdd per block).
// ---------------------------------------------------------------------------
__global__ __launch_bounds__(256) void dwconv_kernel(const float* __restrict__ wdw) {
    __shared__ float img[68 * W_];   // 34,816 B
    __shared__ float warpsum[8];

    const int blk  = blockIdx.x;
    const int half = blk & 1;
    const int bc   = blk >> 1;           // b*QKV + ch
    const int b    = bc / QKV;
    const int ch   = bc % QKV;
    const int r0   = half * 64;          // first output row

    const float* in  = g_qkv + (long)bc * HW;
    float*       out = g_dw  + (long)bc * HW;

    const int t = threadIdx.x;
    // load rows [r0-2, r0+66) with zero fill outside [0,128)
    for (int i = t; i < 68 * W_; i += 256) {
        int y = r0 - 2 + (i >> 7);
        img[i] = (y >= 0 && y < H_) ? in[y * W_ + (i & 127)] : 0.f;
    }
    float w[9];
    #pragma unroll
    for (int i = 0; i < 9; i++) w[i] = wdw[ch * 9 + i];
    __syncthreads();

    const int x0  = (t & 31) * 4;   // 4 consecutive pixels
    const int yy0 = t >> 5;         // 8 row-phases
    float ssq = 0.f;

    for (int yo = yy0; yo < 64; yo += 8) {
        const int y    = r0 + yo;       // global row
        const int srow = yo + 2;        // smem row of center tap
        float o[4] = {0.f, 0.f, 0.f, 0.f};
        #pragma unroll
        for (int ky = 0; ky < 3; ky++) {
            const float* row = &img[(srow + 2 * ky - 2) * W_];
            float r[8];
            #pragma unroll
            for (int j = 0; j < 8; j++) {
                int xx = x0 - 2 + j;
                r[j] = (xx >= 0 && xx < W_) ? row[xx] : 0.f;
            }
            float w0 = w[ky * 3], w1 = w[ky * 3 + 1], w2 = w[ky * 3 + 2];
            #pragma unroll
            for (int j = 0; j < 4; j++)
                o[j] += w0 * r[j] + w1 * r[j + 2] + w2 * r[j + 4];
        }
        #pragma unroll
        for (int j = 0; j < 4; j++) {
            out[y * W_ + x0 + j] = o[j];
            ssq += o[j] * o[j];
        }
    }

    if (ch < 2 * DIM) {   // q or k channel -> accumulate sum of squares
        #pragma unroll
        for (int off = 16; off; off >>= 1)
            ssq += __shfl_xor_sync(0xffffffffu, ssq, off);
        if ((t & 31) == 0) warpsum[t >> 5] = ssq;
        __syncthreads();
        if (t == 0) {
            float s = 0.f;
            #pragma unroll
            for (int i = 0; i < 8; i++) s += warpsum[i];
            float* dst = (ch < DIM) ? &g_ssq[b * DIM + ch]
                                    : &g_ssk[b * DIM + ch - DIM];
            atomicAdd(dst, s);
        }
    }
}

// ---------------------------------------------------------------------------
// Gram matrices S[b,h] = Q[b,h] @ K[b,h]^T  (24x24, K-dim = 16384), split
// over n into 32 partials, atomicAdd into g_S. 64 threads, 3x3 micro-tiles.
// ---------------------------------------------------------------------------
#define ATTN_SPLIT 32
#define ATTN_NB (HW / ATTN_SPLIT)   // 512

__global__ __launch_bounds__(64) void attn_partial_kernel() {
    __shared__ float qs[CH][68];
    __shared__ float ks[CH][68];

    const int bh   = blockIdx.y;           // 0..63
    const int b    = bh >> 3, head = bh & 7;
    const long qbase = ((long)b * QKV + head * CH) * HW;
    const long kbase = ((long)b * QKV + DIM + head * CH) * HW;
    const int nb = blockIdx.x * ATTN_NB;

    const int t  = threadIdx.x;
    const int cb = (t >> 3) * 3;   // 0,3,...,21
    const int db = (t & 7)  * 3;

    float acc[3][3] = {{0.f,0.f,0.f},{0.f,0.f,0.f},{0.f,0.f,0.f}};

    for (int c0 = 0; c0 < ATTN_NB; c0 += 64) {
        __syncthreads();
        for (int i = t; i < CH * 64; i += 64) {
            int row = i >> 6, col = i & 63;
            qs[row][col] = g_dw[qbase + (long)row * HW + nb + c0 + col];
            ks[row][col] = g_dw[kbase + (long)row * HW + nb + c0 + col];
        }
        __syncthreads();
        #pragma unroll
        for (int nn = 0; nn < 64; nn += 4) {
            float4 q[3], k[3];
            #pragma unroll
            for (int i = 0; i < 3; i++) q[i] = *(float4*)&qs[cb + i][nn];
            #pragma unroll
            for (int j = 0; j < 3; j++) k[j] = *(float4*)&ks[db + j][nn];
            #pragma unroll
            for (int i = 0; i < 3; i++)
                #pragma unroll
                for (int j = 0; j < 3; j++)
                    acc[i][j] += q[i].x * k[j].x + q[i].y * k[j].y +
                                 q[i].z * k[j].z + q[i].w * k[j].w;
        }
    }
    #pragma unroll
    for (int i = 0; i < 3; i++)
        #pragma unroll
        for (int j = 0; j < 3; j++)
            atomicAdd(&g_S[(bh * CH + cb + i) * CH + db + j], acc[i][j]);
}

// ---------------------------------------------------------------------------
// Per (b,head): scale Gram by 1/(||q|| ||k||) * temperature, softmax rows,
// then fold into projection:  g_M[b][o][head*24+d] = sum_c Wproj[o][head*24+c]*attn[c][d]
// ---------------------------------------------------------------------------
__global__ __launch_bounds__(256) void softmax_m_kernel(
    const float* __restrict__ wproj, const float* __restrict__ temperature)
{
    __shared__ float a[CH][CH];
    __shared__ float rq[CH], rk[CH];

    const int bh = blockIdx.x;
    const int b = bh >> 3, head = bh & 7;
    const int t = threadIdx.x;

    for (int i = t; i < CH * CH; i += 256)
        a[i / CH][i % CH] = g_S[bh * CH * CH + i];
    if (t < CH) {
        float nq = sqrtf(g_ssq[b * DIM + head * CH + t]);
        rq[t] = 1.f / fmaxf(nq, 1e-12f);
        float nk = sqrtf(g_ssk[b * DIM + head * CH + t]);
        rk[t] = 1.f / fmaxf(nk, 1e-12f);
    }
    __syncthreads();

    if (t < CH) {
        const float temp = temperature[head];
        float row[CH];
        float m = -1e30f;
        #pragma unroll
        for (int d = 0; d < CH; d++) {
            float v = a[t][d] * rq[t] * rk[d] * temp;
            row[d] = v;
            m = fmaxf(m, v);
        }
        float s = 0.f;
        #pragma unroll
        for (int d = 0; d < CH; d++) { row[d] = expf(row[d] - m); s += row[d]; }
        float inv = 1.f / s;
        #pragma unroll
        for (int d = 0; d < CH; d++) a[t][d] = row[d] * inv;
    }
    __syncthreads();

    for (int idx = t; idx < DIM * CH; idx += 256) {
        int o = idx / CH, d = idx % CH;
        float s = 0.f;
        #pragma unroll
        for (int c = 0; c < CH; c++)
            s += wproj[o * DIM + head * CH + c] * a[c][d];
        g_M[(long)b * DIM * DIM + o * DIM + head * CH + d] = s;
    }
}

// ---------------------------------------------------------------------------
extern "C" void kernel_launch(void* const* d_in, const int* in_sizes, int n_in,
                              void* d_out, int out_size)
{
    const float* x     = (const float*)d_in[0];   // [8,192,128,128]
    const float* wqkv  = (const float*)d_in[1];   // [576,192,1,1]
    const float* wdw   = (const float*)d_in[2];   // [576,1,3,3]
    const float* wproj = (const float*)d_in[3];   // [192,192,1,1]
    const float* temp  = (const float*)d_in[4];   // [8,1,1]
    float* out = (float*)d_out;                   // [8,192,128,128]

    // 1) zero accumulators
    zero_kernel<<<36, 1024>>>();

    // 2) qkv = Wqkv @ x  (per batch)
    sgemm_kernel<<<dim3(HW / 128, QKV / 64, B_), 256>>>(0, wqkv, x, nullptr);

    // 3) depthwise conv (+ fused q/k sum-of-squares)
    dwconv_kernel<<<B_ * QKV * 2, 256>>>(wdw);

    // 4) Gram matrices (split-n, atomic accumulate)
    attn_partial_kernel<<<dim3(ATTN_SPLIT, B_ * NH), 64>>>();

    // 5) normalize + softmax + fold into projection matrix
    softmax_m_kernel<<<B_ * NH, 256>>>(wproj, temp);

    // 6) out = M_b @ V  (per batch)
    sgemm_kernel<<<dim3(HW / 128, DIM / 64, B_), 256>>>(1, nullptr, nullptr, out);
}

// round 2
// speedup vs baseline: 2.7601x; 2.7601x over previous
#include <cuda_runtime.h>
#include <cuda_bf16.h>
#include <math.h>
#include <stdint.h>

// Problem constants
#define B_   8
#define DIM  192
#define QKV  576     // 3*DIM
#define NH   8
#define CH   24      // DIM / NH
#define H_   128
#define W_   128
#define HW   16384

// Scratch (device globals; no allocation allowed)
__device__ float g_qkv[B_ * QKV * HW];   // after 1x1 conv
__device__ float g_dw [B_ * QKV * HW];   // after depthwise conv
__device__ float g_ssq[B_ * DIM];        // sum of squares of q rows
__device__ float g_ssk[B_ * DIM];        // sum of squares of k rows
__device__ float g_S  [B_ * NH * CH * CH]; // raw Gram matrices
__device__ float g_M  [B_ * DIM * DIM];  // W_proj @ blockdiag(attn)

// ---------------------------------------------------------------------------
__global__ void zero_kernel() {
    int i = blockIdx.x * blockDim.x + threadIdx.x;
    if (i < B_ * NH * CH * CH) g_S[i] = 0.f;
    if (i < B_ * DIM) { g_ssq[i] = 0.f; g_ssk[i] = 0.f; }
}

// ---------------------------------------------------------------------------
// bf16x3 split tensor-core GEMM: C[M,N] = A[M,K] @ B[K,N], fp32 in/out.
// A·B ≈ Ahi·Bhi + Ahi·Blo + Alo·Bhi  (error ~2^-16 per product)
// Tile: BM=64, BN=128, BK=32. 8 warps, each 32x32. K = DIM = 192.
// mode 0: A = w_qkv,            B = x[z],        C = g_qkv[z]
// mode 1: A = g_M[z],           B = v part of g_dw[z], C = out[z]
// ---------------------------------------------------------------------------
#define BM 64
#define BN 128
#define BK 32
#define LDA_S 40    // bf16 elems per As row (pad 8 -> conflict-free ldmatrix)
#define LDB_S 136   // bf16 elems per Bs row (pad 8 -> conflict-free ldmatrix)

__device__ __forceinline__ void ldsm4(uint32_t &r0, uint32_t &r1, uint32_t &r2,
                                      uint32_t &r3, uint32_t addr) {
    asm volatile("ldmatrix.sync.aligned.m8n8.x4.shared.b16 {%0,%1,%2,%3}, [%4];"
                 : "=r"(r0), "=r"(r1), "=r"(r2), "=r"(r3) : "r"(addr));
}
__device__ __forceinline__ void ldsm4t(uint32_t &r0, uint32_t &r1, uint32_t &r2,
                                       uint32_t &r3, uint32_t addr) {
    asm volatile("ldmatrix.sync.aligned.m8n8.x4.trans.shared.b16 {%0,%1,%2,%3}, [%4];"
                 : "=r"(r0), "=r"(r1), "=r"(r2), "=r"(r3) : "r"(addr));
}
__device__ __forceinline__ void mma16816(float c[4], uint32_t a0, uint32_t a1,
                                         uint32_t a2, uint32_t a3,
                                         uint32_t b0, uint32_t b1) {
    asm volatile(
        "mma.sync.aligned.m16n8k16.row.col.f32.bf16.bf16.f32 "
        "{%0,%1,%2,%3}, {%4,%5,%6,%7}, {%8,%9}, {%0,%1,%2,%3};"
        : "+f"(c[0]), "+f"(c[1]), "+f"(c[2]), "+f"(c[3])
        : "r"(a0), "r"(a1), "r"(a2), "r"(a3), "r"(b0), "r"(b1));
}
__device__ __forceinline__ void cvt_split(float x, __nv_bfloat16 &hi, __nv_bfloat16 &lo) {
    hi = __float2bfloat16(x);
    lo = __float2bfloat16(x - __bfloat162float(hi));
}

__global__ __launch_bounds__(256) void gemm3x_kernel(
    int mode, const float* __restrict__ Aext, const float* __restrict__ Bext,
    float* __restrict__ Cext)
{
    __shared__ __align__(16) __nv_bfloat16 As[2][BM][LDA_S];  // [hi/lo]
    __shared__ __align__(16) __nv_bfloat16 Bs[2][BK][LDB_S];

    const int z = blockIdx.z;
    const float* A;
    const float* Bb;
    float* Cb;
    if (mode == 0) {
        A  = Aext;                                  // [576][192]
        Bb = Bext + (long)z * DIM * HW;
        Cb = g_qkv + (long)z * QKV * HW;
    } else {
        A  = g_M + (long)z * DIM * DIM;             // [192][192]
        Bb = g_dw + (long)z * QKV * HW + (long)(2 * DIM) * HW;  // v
        Cb = Cext + (long)z * DIM * HW;
    }
    const float* Ab = A + (long)blockIdx.y * BM * DIM;
    Bb += blockIdx.x * BN;
    Cb += (long)blockIdx.y * BM * HW + blockIdx.x * BN;

    const int t    = threadIdx.x;
    const int lane = t & 31;
    const int warp = t >> 5;
    const int wm   = (warp >> 2) * 32;   // warp m offset: 0/32
    const int wn   = (warp & 3) * 32;    // warp n offset: 0/32/64/96

    // ldmatrix source addresses (lane-dependent parts)
    const int lr = lane & 15;          // row within 16
    const int lc = (lane >> 4) * 8;    // col half

    float acc[2][4][4];                 // [mtile][n8][4]
    #pragma unroll
    for (int i = 0; i < 2; i++)
        #pragma unroll
        for (int j = 0; j < 4; j++)
            #pragma unroll
            for (int r = 0; r < 4; r++) acc[i][j][r] = 0.f;

    // global-load index precompute
    const int a_row = t >> 3;          // 0..31 (two batches -> 64 rows)
    const int a_col = (t & 7) * 4;     // 0..28
    const int b_row = t >> 5;          // 0..7 (four batches -> 32 rows)
    const int b_col = (t & 31) * 4;    // 0..124

    for (int k0 = 0; k0 < DIM; k0 += BK) {
        // ---- load + convert A tile (64x32) ----
        #pragma unroll
        for (int i = 0; i < 2; i++) {
            int r = a_row + i * 32;
            float4 v = *(const float4*)&Ab[(long)r * DIM + k0 + a_col];
            __nv_bfloat16 h0,h1,h2,h3,l0,l1,l2,l3;
            cvt_split(v.x,h0,l0); cvt_split(v.y,h1,l1);
            cvt_split(v.z,h2,l2); cvt_split(v.w,h3,l3);
            *(__nv_bfloat162*)&As[0][r][a_col]     = __nv_bfloat162(h0,h1);
            *(__nv_bfloat162*)&As[0][r][a_col + 2] = __nv_bfloat162(h2,h3);
            *(__nv_bfloat162*)&As[1][r][a_col]     = __nv_bfloat162(l0,l1);
            *(__nv_bfloat162*)&As[1][r][a_col + 2] = __nv_bfloat162(l2,l3);
        }
        // ---- load + convert B tile (32x128) ----
        #pragma unroll
        for (int i = 0; i < 4; i++) {
            int r = b_row + i * 8;
            float4 v = *(const float4*)&Bb[(long)(k0 + r) * HW + b_col];
            __nv_bfloat16 h0,h1,h2,h3,l0,l1,l2,l3;
            cvt_split(v.x,h0,l0); cvt_split(v.y,h1,l1);
            cvt_split(v.z,h2,l2); cvt_split(v.w,h3,l3);
            *(__nv_bfloat162*)&Bs[0][r][b_col]     = __nv_bfloat162(h0,h1);
            *(__nv_bfloat162*)&Bs[0][r][b_col + 2] = __nv_bfloat162(h2,h3);
            *(__nv_bfloat162*)&Bs[1][r][b_col]     = __nv_bfloat162(l0,l1);
            *(__nv_bfloat162*)&Bs[1][r][b_col + 2] = __nv_bfloat162(l2,l3);
        }
        __syncthreads();

        #pragma unroll
        for (int kk = 0; kk < BK; kk += 16) {
            uint32_t a[2][2][4];   // [hi/lo][mtile][4]
            uint32_t b[2][2][4];   // [hi/lo][ncall(16)][4]
            #pragma unroll
            for (int v = 0; v < 2; v++) {
                #pragma unroll
                for (int mt = 0; mt < 2; mt++) {
                    uint32_t addr = __cvta_generic_to_shared(
                        &As[v][wm + mt * 16 + lr][kk + lc]);
                    ldsm4(a[v][mt][0], a[v][mt][1], a[v][mt][2], a[v][mt][3], addr);
                }
                #pragma unroll
                for (int nc = 0; nc < 2; nc++) {
                    uint32_t addr = __cvta_generic_to_shared(
                        &Bs[v][kk + lr][wn + nc * 16 + lc]);
                    ldsm4t(b[v][nc][0], b[v][nc][1], b[v][nc][2], b[v][nc][3], addr);
                }
            }
            #pragma unroll
            for (int mt = 0; mt < 2; mt++)
                #pragma unroll
                for (int j = 0; j < 4; j++) {
                    uint32_t bh0 = b[0][j >> 1][(j & 1) * 2];
                    uint32_t bh1 = b[0][j >> 1][(j & 1) * 2 + 1];
                    uint32_t bl0 = b[1][j >> 1][(j & 1) * 2];
                    uint32_t bl1 = b[1][j >> 1][(j & 1) * 2 + 1];
                    // hi*hi
                    mma16816(acc[mt][j], a[0][mt][0], a[0][mt][1], a[0][mt][2],
                             a[0][mt][3], bh0, bh1);
                    // hi*lo
                    mma16816(acc[mt][j], a[0][mt][0], a[0][mt][1], a[0][mt][2],
                             a[0][mt][3], bl0, bl1);
                    // lo*hi
                    mma16816(acc[mt][j], a[1][mt][0], a[1][mt][1], a[1][mt][2],
                             a[1][mt][3], bh0, bh1);
                }
        }
        __syncthreads();
    }

    // ---- epilogue ----
    const int er = lane >> 2;          // 0..7
    const int ec = (lane & 3) * 2;     // 0..6
    #pragma unroll
    for (int mt = 0; mt < 2; mt++) {
        #pragma unroll
        for (int j = 0; j < 4; j++) {
            long base = (long)(wm + mt * 16 + er) * HW + wn + j * 8 + ec;
            *(float2*)&Cb[base]            = make_float2(acc[mt][j][0], acc[mt][j][1]);
            *(float2*)&Cb[base + 8 * HW]   = make_float2(acc[mt][j][2], acc[mt][j][3]);
        }
    }
}

// ---------------------------------------------------------------------------
// Depthwise 3x3, dilation 2, pad 2. One block = (b, ch, half-image of 64 rows).
// Fused q/k sum-of-squares.
// ---------------------------------------------------------------------------
__global__ __launch_bounds__(256) void dwconv_kernel(const float* __restrict__ wdw) {
    __shared__ float img[68 * W_];
    __shared__ float warpsum[8];

    const int blk  = blockIdx.x;
    const int half = blk & 1;
    const int bc   = blk >> 1;
    const int b    = bc / QKV;
    const int ch   = bc % QKV;
    const int r0   = half * 64;

    const float* in  = g_qkv + (long)bc * HW;
    float*       out = g_dw  + (long)bc * HW;

    const int t = threadIdx.x;
    for (int i = t; i < 68 * W_; i += 256) {
        int y = r0 - 2 + (i >> 7);
        img[i] = (y >= 0 && y < H_) ? in[y * W_ + (i & 127)] : 0.f;
    }
    float w[9];
    #pragma unroll
    for (int i = 0; i < 9; i++) w[i] = wdw[ch * 9 + i];
    __syncthreads();

    const int x0  = (t & 31) * 4;
    const int yy0 = t >> 5;
    float ssq = 0.f;

    for (int yo = yy0; yo < 64; yo += 8) {
        const int y    = r0 + yo;
        const int srow = yo + 2;
        float o[4] = {0.f, 0.f, 0.f, 0.f};
        #pragma unroll
        for (int ky = 0; ky < 3; ky++) {
            const float* row = &img[(srow + 2 * ky - 2) * W_];
            float r[8];
            #pragma unroll
            for (int j = 0; j < 8; j++) {
                int xx = x0 - 2 + j;
                r[j] = (xx >= 0 && xx < W_) ? row[xx] : 0.f;
            }
            float w0 = w[ky * 3], w1 = w[ky * 3 + 1], w2 = w[ky * 3 + 2];
            #pragma unroll
            for (int j = 0; j < 4; j++)
                o[j] += w0 * r[j] + w1 * r[j + 2] + w2 * r[j + 4];
        }
        #pragma unroll
        for (int j = 0; j < 4; j++) {
            out[y * W_ + x0 + j] = o[j];
            ssq += o[j] * o[j];
        }
    }

    if (ch < 2 * DIM) {
        #pragma unroll
        for (int off = 16; off; off >>= 1)
            ssq += __shfl_xor_sync(0xffffffffu, ssq, off);
        if ((t & 31) == 0) warpsum[t >> 5] = ssq;
        __syncthreads();
        if (t == 0) {
            float s = 0.f;
            #pragma unroll
            for (int i = 0; i < 8; i++) s += warpsum[i];
            float* dst = (ch < DIM) ? &g_ssq[b * DIM + ch]
                                    : &g_ssk[b * DIM + ch - DIM];
            atomicAdd(dst, s);
        }
    }
}

// ---------------------------------------------------------------------------
// Gram matrices S[b,h] = Q[b,h] @ K[b,h]^T  (24x24, n = 16384), split over n.
// ---------------------------------------------------------------------------
#define ATTN_SPLIT 32
#define ATTN_NB (HW / ATTN_SPLIT)

__global__ __launch_bounds__(64) void attn_partial_kernel() {
    __shared__ float qs[CH][68];
    __shared__ float ks[CH][68];

    const int bh   = blockIdx.y;
    const int b    = bh >> 3, head = bh & 7;
    const long qbase = ((long)b * QKV + head * CH) * HW;
    const long kbase = ((long)b * QKV + DIM + head * CH) * HW;
    const int nb = blockIdx.x * ATTN_NB;

    const int t  = threadIdx.x;
    const int cb = (t >> 3) * 3;
    const int db = (t & 7)  * 3;

    float acc[3][3] = {{0.f,0.f,0.f},{0.f,0.f,0.f},{0.f,0.f,0.f}};

    for (int c0 = 0; c0 < ATTN_NB; c0 += 64) {
        __syncthreads();
        for (int i = t; i < CH * 64; i += 64) {
            int row = i >> 6, col = i & 63;
            qs[row][col] = g_dw[qbase + (long)row * HW + nb + c0 + col];
            ks[row][col] = g_dw[kbase + (long)row * HW + nb + c0 + col];
        }
        __syncthreads();
        #pragma unroll
        for (int nn = 0; nn < 64; nn += 4) {
            float4 q[3], k[3];
            #pragma unroll
            for (int i = 0; i < 3; i++) q[i] = *(float4*)&qs[cb + i][nn];
            #pragma unroll
            for (int j = 0; j < 3; j++) k[j] = *(float4*)&ks[db + j][nn];
            #pragma unroll
            for (int i = 0; i < 3; i++)
                #pragma unroll
                for (int j = 0; j < 3; j++)
                    acc[i][j] += q[i].x * k[j].x + q[i].y * k[j].y +
                                 q[i].z * k[j].z + q[i].w * k[j].w;
        }
    }
    #pragma unroll
    for (int i = 0; i < 3; i++)
        #pragma unroll
        for (int j = 0; j < 3; j++)
            atomicAdd(&g_S[(bh * CH + cb + i) * CH + db + j], acc[i][j]);
}

// ---------------------------------------------------------------------------
__global__ __launch_bounds__(256) void softmax_m_kernel(
    const float* __restrict__ wproj, const float* __restrict__ temperature)
{
    __shared__ float a[CH][CH];
    __shared__ float rq[CH], rk[CH];

    const int bh = blockIdx.x;
    const int b = bh >> 3, head = bh & 7;
    const int t = threadIdx.x;

    for (int i = t; i < CH * CH; i += 256)
        a[i / CH][i % CH] = g_S[bh * CH * CH + i];
    if (t < CH) {
        float nq = sqrtf(g_ssq[b * DIM + head * CH + t]);
        rq[t] = 1.f / fmaxf(nq, 1e-12f);
        float nk = sqrtf(g_ssk[b * DIM + head * CH + t]);
        rk[t] = 1.f / fmaxf(nk, 1e-12f);
    }
    __syncthreads();

    if (t < CH) {
        const float temp = temperature[head];
        float row[CH];
        float m = -1e30f;
        #pragma unroll
        for (int d = 0; d < CH; d++) {
            float v = a[t][d] * rq[t] * rk[d] * temp;
            row[d] = v;
            m = fmaxf(m, v);
        }
        float s = 0.f;
        #pragma unroll
        for (int d = 0; d < CH; d++) { row[d] = expf(row[d] - m); s += row[d]; }
        float inv = 1.f / s;
        #pragma unroll
        for (int d = 0; d < CH; d++) a[t][d] = row[d] * inv;
    }
    __syncthreads();

    for (int idx = t; idx < DIM * CH; idx += 256) {
        int o = idx / CH, d = idx % CH;
        float s = 0.f;
        #pragma unroll
        for (int c = 0; c < CH; c++)
            s += wproj[o * DIM + head * CH + c] * a[c][d];
        g_M[(long)b * DIM * DIM + o * DIM + head * CH + d] = s;
    }
}

// ---------------------------------------------------------------------------
extern "C" void kernel_launch(void* const* d_in, const int* in_sizes, int n_in,
                              void* d_out, int out_size)
{
    const float* x     = (const float*)d_in[0];
    const float* wqkv  = (const float*)d_in[1];
    const float* wdw   = (const float*)d_in[2];
    const float* wproj = (const float*)d_in[3];
    const float* temp  = (const float*)d_in[4];
    float* out = (float*)d_out;

    zero_kernel<<<36, 1024>>>();

    // qkv = Wqkv @ x  (tensor cores, bf16x3)
    gemm3x_kernel<<<dim3(HW / BN, QKV / BM, B_), 256>>>(0, wqkv, x, nullptr);

    dwconv_kernel<<<B_ * QKV * 2, 256>>>(wdw);

    attn_partial_kernel<<<dim3(ATTN_SPLIT, B_ * NH), 64>>>();

    softmax_m_kernel<<<B_ * NH, 256>>>(wproj, temp);

    // out = M_b @ V  (tensor cores, bf16x3)
    gemm3x_kernel<<<dim3(HW / BN, DIM / BM, B_), 256>>>(1, nullptr, nullptr, out);
}